// round 7
// baseline (speedup 1.0000x reference)
#include <cuda_runtime.h>

#define D 128
#define MAXN 50176        // padded node capacity (actual N = 50000)
#define MAXE 600000

// ---------------- scratch (no allocs allowed) ----------------
__device__ int   g_cnt[MAXN];          // in-degree counts
__device__ int   g_fill[MAXN];         // fill cursors for CSR build
__device__ int   g_row[MAXN + 1];      // CSR row offsets (by destination)
__device__ int   g_csrc[MAXE];         // CSR column = source node ids
__device__ float g_inv[MAXN];          // 1 / max(deg, 1)
__device__ float g_hop1[MAXN * D];
__device__ float g_hop2[MAXN * D];

// ---------------- zero the small int arrays ----------------
__global__ void zero_kernel() {
    int i = blockIdx.x * blockDim.x + threadIdx.x;
    if (i < MAXN) { g_cnt[i] = 0; g_fill[i] = 0; }
}

// ---------------- in-degree histogram ----------------
__global__ void degree_kernel(const int* __restrict__ ei, int E) {
    int e = blockIdx.x * blockDim.x + threadIdx.x;
    if (e < E) {
        int d = ei[E + e];
        atomicAdd(&g_cnt[d], 1);
    }
}

// ---------------- exclusive prefix sum over MAXN counts (single block) ----------------
__global__ void scan_kernel() {
    __shared__ int sh[1024];
    const int CH = MAXN / 1024;        // 49, exact
    int t = threadIdx.x;
    int base = t * CH;

    int s = 0;
    for (int i = 0; i < CH; i++) s += g_cnt[base + i];
    sh[t] = s;
    __syncthreads();

    for (int off = 1; off < 1024; off <<= 1) {
        int v = (t >= off) ? sh[t - off] : 0;
        __syncthreads();
        sh[t] += v;
        __syncthreads();
    }

    int run = (t == 0) ? 0 : sh[t - 1];
    for (int i = 0; i < CH; i++) {
        int idx = base + i;
        int c = g_cnt[idx];
        g_row[idx] = run;
        g_inv[idx] = 1.0f / fmaxf((float)c, 1.0f);
        run += c;
    }
    if (t == 1023) g_row[MAXN] = run;
}

// ---------------- CSR fill ----------------
__global__ void fill_kernel(const int* __restrict__ ei, int E) {
    int e = blockIdx.x * blockDim.x + threadIdx.x;
    if (e < E) {
        int s = ei[e];
        int d = ei[E + e];
        int pos = g_row[d] + atomicAdd(&g_fill[d], 1);
        g_csrc[pos] = s;
    }
}

// ---------------- mean aggregation (pull): one warp per dst node ----------------
__global__ void hop_kernel(const float* __restrict__ x, int pass, int n) {
    int w = (blockIdx.x * blockDim.x + threadIdx.x) >> 5;
    if (w >= n) return;
    int lane = threadIdx.x & 31;

    const float4* in = (pass == 0) ? (const float4*)x : (const float4*)g_hop1;
    float*        op = (pass == 0) ? g_hop1 : g_hop2;

    int beg = g_row[w];
    int end = g_row[w + 1];

    float ax = 0.f, ay = 0.f, az = 0.f, aw = 0.f;
    int j = beg;
    for (; j + 4 <= end; j += 4) {
        int s0 = __ldg(&g_csrc[j + 0]);
        int s1 = __ldg(&g_csrc[j + 1]);
        int s2 = __ldg(&g_csrc[j + 2]);
        int s3 = __ldg(&g_csrc[j + 3]);
        float4 v0 = __ldg(in + (size_t)s0 * 32 + lane);
        float4 v1 = __ldg(in + (size_t)s1 * 32 + lane);
        float4 v2 = __ldg(in + (size_t)s2 * 32 + lane);
        float4 v3 = __ldg(in + (size_t)s3 * 32 + lane);
        ax += v0.x; ay += v0.y; az += v0.z; aw += v0.w;
        ax += v1.x; ay += v1.y; az += v1.z; aw += v1.w;
        ax += v2.x; ay += v2.y; az += v2.z; aw += v2.w;
        ax += v3.x; ay += v3.y; az += v3.z; aw += v3.w;
    }
    for (; j < end; j++) {
        int s0 = __ldg(&g_csrc[j]);
        float4 v0 = __ldg(in + (size_t)s0 * 32 + lane);
        ax += v0.x; ay += v0.y; az += v0.z; aw += v0.w;
    }

    float inv = g_inv[w];
    float4 r = make_float4(ax * inv, ay * inv, az * inv, aw * inv);
    *((float4*)op + (size_t)w * 32 + lane) = r;
}

// ---------------- packed f32x2 helpers ----------------
__device__ __forceinline__ unsigned long long pk2(float lo, float hi) {
    unsigned long long r;
    asm("mov.b64 %0, {%1, %2};" : "=l"(r) : "f"(lo), "f"(hi));
    return r;
}
__device__ __forceinline__ void fma2(unsigned long long& d,
                                     unsigned long long a,
                                     unsigned long long b) {
    asm("fma.rn.f32x2 %0, %1, %2, %0;" : "+l"(d) : "l"(a), "l"(b));
}
__device__ __forceinline__ float fold2(unsigned long long p) {
    float lo, hi;
    asm("mov.b64 {%0, %1}, %2;" : "=f"(lo), "=f"(hi) : "l"(p));
    return lo + hi;
}

// ---------------- fused concat-GEMM: out = [x|hop1|hop2] @ W^T + b ----------------
// BM=128 nodes, BN=128 outputs, BK=32. 512 threads, 8x4 outputs per thread.
// K paired into f32x2 lanes; register-prefetch double buffering of tile loads.
#define AK 36   // padded k-stride of As (16B-store aligned, 8B-load aligned)
__global__ __launch_bounds__(512, 1)
void gemm_kernel(const float* __restrict__ x,
                 const float* __restrict__ W,     // [128, 384] row-major
                 const float* __restrict__ bias,  // [128]
                 float* __restrict__ out, int n) {
    __shared__ float As[128][AK];   // As[m][k]  (k-contiguous per node row)
    __shared__ float Bs[32][128];   // Bs[k][o]  (transposed)

    int tid  = threadIdx.x;
    int m0   = blockIdx.x * 128;
    int tcol = tid & 31;            // output group: o = tcol*4 .. +3
    int trow = tid >> 5;            // node group:   m = trow*8 .. +7

    unsigned long long acc[8][4];
#pragma unroll
    for (int i = 0; i < 8; i++)
#pragma unroll
        for (int jj = 0; jj < 4; jj++) acc[i][jj] = 0ULL;

    int l_k4 = (tid & 7) * 4;       // loader: k offset within tile
    int l_r  = tid >> 3;            // loader: row 0..63, +64 on pass 2

    float4 av[2], wv[2];

    // prefetch tile kt = 0 (A source = x, ka = 0..)
#pragma unroll
    for (int p = 0; p < 2; p++) {
        int r = l_r + p * 64;
        int gn = m0 + r;
        av[p] = make_float4(0.f, 0.f, 0.f, 0.f);
        if (gn < n) av[p] = __ldg((const float4*)(x + (size_t)gn * 128 + l_k4));
        wv[p] = __ldg((const float4*)(W + (size_t)r * 384 + l_k4));
    }

#pragma unroll 1
    for (int kt = 0; kt < 12; kt++) {
        __syncthreads();  // everyone done reading previous tile
#pragma unroll
        for (int p = 0; p < 2; p++) {
            int r = l_r + p * 64;
            *(float4*)&As[r][l_k4] = av[p];        // k-contiguous store
            Bs[l_k4 + 0][r] = wv[p].x;             // transposed store
            Bs[l_k4 + 1][r] = wv[p].y;
            Bs[l_k4 + 2][r] = wv[p].z;
            Bs[l_k4 + 3][r] = wv[p].w;
        }
        __syncthreads();

        // issue next tile's global loads; compute below hides their latency
        if (kt < 11) {
            int k0n = (kt + 1) * 32;
            const float* A = (k0n < 128) ? x : (k0n < 256) ? g_hop1 : g_hop2;
            int ka = k0n & 127;
#pragma unroll
            for (int p = 0; p < 2; p++) {
                int r = l_r + p * 64;
                int gn = m0 + r;
                av[p] = make_float4(0.f, 0.f, 0.f, 0.f);
                if (gn < n)
                    av[p] = __ldg((const float4*)(A + (size_t)gn * 128 + ka + l_k4));
                wv[p] = __ldg((const float4*)(W + (size_t)r * 384 + k0n + l_k4));
            }
        }

#pragma unroll
        for (int kk = 0; kk < 32; kk += 2) {
            float4 b0 = *(const float4*)&Bs[kk + 0][tcol * 4];
            float4 b1 = *(const float4*)&Bs[kk + 1][tcol * 4];
            unsigned long long pb0 = pk2(b0.x, b1.x);
            unsigned long long pb1 = pk2(b0.y, b1.y);
            unsigned long long pb2 = pk2(b0.z, b1.z);
            unsigned long long pb3 = pk2(b0.w, b1.w);
#pragma unroll
            for (int i = 0; i < 8; i++) {
                unsigned long long aa =
                    *(const unsigned long long*)&As[trow * 8 + i][kk];  // broadcast LDS.64
                fma2(acc[i][0], aa, pb0);
                fma2(acc[i][1], aa, pb1);
                fma2(acc[i][2], aa, pb2);
                fma2(acc[i][3], aa, pb3);
            }
        }
    }

    float4 bb = __ldg((const float4*)(bias + tcol * 4));
#pragma unroll
    for (int i = 0; i < 8; i++) {
        int gn = m0 + trow * 8 + i;
        if (gn < n) {
            float4 r = make_float4(fold2(acc[i][0]) + bb.x,
                                   fold2(acc[i][1]) + bb.y,
                                   fold2(acc[i][2]) + bb.z,
                                   fold2(acc[i][3]) + bb.w);
            *(float4*)(out + (size_t)gn * 128 + tcol * 4) = r;
        }
    }
}

// ---------------- launch ----------------
extern "C" void kernel_launch(void* const* d_in, const int* in_sizes, int n_in,
                              void* d_out, int out_size) {
    const float* x    = (const float*)d_in[0];
    const int*   ei   = (const int*)d_in[1];      // int32 (JAX x64 disabled)
    const float* W    = (const float*)d_in[2];
    const float* bias = (const float*)d_in[3];
    float*       out  = (float*)d_out;

    int n = in_sizes[0] / D;      // 50000
    int E = in_sizes[1] / 2;      // 600000

    // CSR build (by destination)
    zero_kernel<<<(MAXN + 255) / 256, 256>>>();
    degree_kernel<<<(E + 255) / 256, 256>>>(ei, E);
    scan_kernel<<<1, 1024>>>();
    fill_kernel<<<(E + 255) / 256, 256>>>(ei, E);

    // two mean-propagation hops (pull / gather, no float atomics)
    int hop_blocks = (n * 32 + 255) / 256;
    hop_kernel<<<hop_blocks, 256>>>(x, 0, n);
    hop_kernel<<<hop_blocks, 256>>>(x, 1, n);

    // fused concat + linear (f32x2 packed FMA, 512 threads, reg prefetch)
    gemm_kernel<<<(n + 127) / 128, 512>>>(x, W, bias, out, n);
}

// round 9
// speedup vs baseline: 1.6059x; 1.6059x over previous
#include <cuda_runtime.h>
#include <cuda_bf16.h>
#include <cstdint>

#define D 128
#define MAXN 50176        // padded node capacity (actual N = 50000)
#define MAXE 600000

// ---------------- scratch (no allocs allowed) ----------------
__device__ int   g_cnt[MAXN];
__device__ int   g_fill[MAXN];
__device__ int   g_row[MAXN + 1];
__device__ int   g_csrc[MAXE];
__device__ float g_inv[MAXN];
__device__ float g_hop1[MAXN * D];
__device__ float g_hop2[MAXN * D];

// ---------------- zero the small int arrays ----------------
__global__ void zero_kernel() {
    int i = blockIdx.x * blockDim.x + threadIdx.x;
    if (i < MAXN) { g_cnt[i] = 0; g_fill[i] = 0; }
}

// ---------------- in-degree histogram ----------------
__global__ void degree_kernel(const int* __restrict__ ei, int E) {
    int e = blockIdx.x * blockDim.x + threadIdx.x;
    if (e < E) atomicAdd(&g_cnt[ei[E + e]], 1);
}

// ---------------- exclusive prefix sum (single block) ----------------
__global__ void scan_kernel() {
    __shared__ int sh[1024];
    const int CH = MAXN / 1024;        // 49
    int t = threadIdx.x;
    int base = t * CH;

    int s = 0;
    for (int i = 0; i < CH; i++) s += g_cnt[base + i];
    sh[t] = s;
    __syncthreads();
    for (int off = 1; off < 1024; off <<= 1) {
        int v = (t >= off) ? sh[t - off] : 0;
        __syncthreads();
        sh[t] += v;
        __syncthreads();
    }
    int run = (t == 0) ? 0 : sh[t - 1];
    for (int i = 0; i < CH; i++) {
        int idx = base + i;
        int c = g_cnt[idx];
        g_row[idx] = run;
        g_inv[idx] = 1.0f / fmaxf((float)c, 1.0f);
        run += c;
    }
    if (t == 1023) g_row[MAXN] = run;
}

// ---------------- CSR fill ----------------
__global__ void fill_kernel(const int* __restrict__ ei, int E) {
    int e = blockIdx.x * blockDim.x + threadIdx.x;
    if (e < E) {
        int s = ei[e];
        int d = ei[E + e];
        int pos = g_row[d] + atomicAdd(&g_fill[d], 1);
        g_csrc[pos] = s;
    }
}

// ---------------- mean aggregation (pull): one warp per dst node ----------------
__global__ void hop_kernel(const float* __restrict__ x, int pass, int n) {
    int w = (blockIdx.x * blockDim.x + threadIdx.x) >> 5;
    if (w >= n) return;
    int lane = threadIdx.x & 31;

    const float4* in = (pass == 0) ? (const float4*)x : (const float4*)g_hop1;
    float*        op = (pass == 0) ? g_hop1 : g_hop2;

    int beg = g_row[w];
    int end = g_row[w + 1];

    float ax = 0.f, ay = 0.f, az = 0.f, aw = 0.f;
    int j = beg;
    for (; j + 4 <= end; j += 4) {
        int s0 = __ldg(&g_csrc[j + 0]);
        int s1 = __ldg(&g_csrc[j + 1]);
        int s2 = __ldg(&g_csrc[j + 2]);
        int s3 = __ldg(&g_csrc[j + 3]);
        float4 v0 = __ldg(in + (size_t)s0 * 32 + lane);
        float4 v1 = __ldg(in + (size_t)s1 * 32 + lane);
        float4 v2 = __ldg(in + (size_t)s2 * 32 + lane);
        float4 v3 = __ldg(in + (size_t)s3 * 32 + lane);
        ax += v0.x; ay += v0.y; az += v0.z; aw += v0.w;
        ax += v1.x; ay += v1.y; az += v1.z; aw += v1.w;
        ax += v2.x; ay += v2.y; az += v2.z; aw += v2.w;
        ax += v3.x; ay += v3.y; az += v3.z; aw += v3.w;
    }
    for (; j < end; j++) {
        int s0 = __ldg(&g_csrc[j]);
        float4 v0 = __ldg(in + (size_t)s0 * 32 + lane);
        ax += v0.x; ay += v0.y; az += v0.z; aw += v0.w;
    }
    float inv = g_inv[w];
    float4 r = make_float4(ax * inv, ay * inv, az * inv, aw * inv);
    *((float4*)op + (size_t)w * 32 + lane) = r;
}

// ---------------- bf16 split helpers ----------------
__device__ __forceinline__ void split2(float f0, float f1, uint32_t& hi, uint32_t& lo) {
    __nv_bfloat16 h0 = __float2bfloat16(f0);
    __nv_bfloat16 h1 = __float2bfloat16(f1);
    __nv_bfloat16 l0 = __float2bfloat16(f0 - __bfloat162float(h0));
    __nv_bfloat16 l1 = __float2bfloat16(f1 - __bfloat162float(h1));
    hi = (uint32_t)__bfloat16_as_ushort(h0) | ((uint32_t)__bfloat16_as_ushort(h1) << 16);
    lo = (uint32_t)__bfloat16_as_ushort(l0) | ((uint32_t)__bfloat16_as_ushort(l1) << 16);
}

__device__ __forceinline__ void mma_bf16(float* c, const uint32_t* a, const uint32_t* b) {
    asm volatile(
        "mma.sync.aligned.m16n8k16.row.col.f32.bf16.bf16.f32 "
        "{%0,%1,%2,%3}, {%4,%5,%6,%7}, {%8,%9}, {%0,%1,%2,%3};"
        : "+f"(c[0]), "+f"(c[1]), "+f"(c[2]), "+f"(c[3])
        : "r"(a[0]), "r"(a[1]), "r"(a[2]), "r"(a[3]), "r"(b[0]), "r"(b[1]));
}

// ---------------- HMMA split-bf16 fused concat-GEMM ----------------
// out = [x|hop1|hop2] @ W^T + b.  CTA: 128 nodes x 128 outs. 8 warps, warp 32x64.
// 3 passes per k-step: Ahi*Bhi + Alo*Bhi + Ahi*Blo (lo*lo dropped, ~2^-18).
#define SSTR 40   // padded bf16 row stride (conflict-free fragment LDS)
__global__ __launch_bounds__(256, 2)
void hmma_gemm_kernel(const float* __restrict__ x,
                      const float* __restrict__ W,     // [128, 384]
                      const float* __restrict__ bias,  // [128]
                      float* __restrict__ out, int n) {
    __shared__ __nv_bfloat16 Ahi[128][SSTR], Alo[128][SSTR];
    __shared__ __nv_bfloat16 Bhi[128][SSTR], Blo[128][SSTR];

    int tid = threadIdx.x;
    int wid = tid >> 5, lane = tid & 31;
    int wm = wid & 3;            // warp row:   m in [wm*32, +32)
    int wn = wid >> 2;           // warp col:   o in [wn*64, +64)
    int g = lane >> 2, tig = lane & 3;
    int m0 = blockIdx.x * 128;

    float acc[2][8][4];
#pragma unroll
    for (int mt = 0; mt < 2; mt++)
#pragma unroll
        for (int nt = 0; nt < 8; nt++)
#pragma unroll
            for (int q = 0; q < 4; q++) acc[mt][nt][q] = 0.f;

    int lrow = tid >> 1;                 // loader row 0..127
    int lh   = (tid & 1) * 16;           // k half within 32-chunk
    bool avalid = (m0 + lrow) < n;

#pragma unroll 1
    for (int kt = 0; kt < 12; kt++) {
        const float* A = (kt < 4) ? x : (kt < 8) ? g_hop1 : g_hop2;
        int ka = (kt & 3) * 32;

        float4 av[4], wv[4];
        const float4* ap = (const float4*)(A + (size_t)(m0 + lrow) * 128 + ka + lh);
        const float4* wp = (const float4*)(W + (size_t)lrow * 384 + kt * 32 + lh);
#pragma unroll
        for (int q = 0; q < 4; q++) {
            av[q] = avalid ? __ldg(ap + q) : make_float4(0.f, 0.f, 0.f, 0.f);
            wv[q] = __ldg(wp + q);
        }

        __syncthreads();   // previous tile fully consumed
#pragma unroll
        for (int q = 0; q < 4; q++) {
            uint32_t h0, l0, h1, l1;
            int kc = lh + q * 4;
            split2(av[q].x, av[q].y, h0, l0);
            split2(av[q].z, av[q].w, h1, l1);
            *(uint32_t*)&Ahi[lrow][kc]     = h0;
            *(uint32_t*)&Ahi[lrow][kc + 2] = h1;
            *(uint32_t*)&Alo[lrow][kc]     = l0;
            *(uint32_t*)&Alo[lrow][kc + 2] = l1;
            split2(wv[q].x, wv[q].y, h0, l0);
            split2(wv[q].z, wv[q].w, h1, l1);
            *(uint32_t*)&Bhi[lrow][kc]     = h0;
            *(uint32_t*)&Bhi[lrow][kc + 2] = h1;
            *(uint32_t*)&Blo[lrow][kc]     = l0;
            *(uint32_t*)&Blo[lrow][kc + 2] = l1;
        }
        __syncthreads();

#pragma unroll
        for (int ks = 0; ks < 2; ks++) {
            int kb = ks * 16 + tig * 2;

            // A fragments (hi for both m-tiles kept live across the Blo pass)
            uint32_t afh[2][4], afl[4];
#pragma unroll
            for (int mt = 0; mt < 2; mt++) {
                int am = wm * 32 + mt * 16 + g;
                afh[mt][0] = *(const uint32_t*)&Ahi[am][kb];
                afh[mt][1] = *(const uint32_t*)&Ahi[am + 8][kb];
                afh[mt][2] = *(const uint32_t*)&Ahi[am][kb + 8];
                afh[mt][3] = *(const uint32_t*)&Ahi[am + 8][kb + 8];
            }

            uint32_t bf[8][2];
#pragma unroll
            for (int nt = 0; nt < 8; nt++) {
                int nn = wn * 64 + nt * 8 + g;
                bf[nt][0] = *(const uint32_t*)&Bhi[nn][kb];
                bf[nt][1] = *(const uint32_t*)&Bhi[nn][kb + 8];
            }
            // pass 1+2: Ahi*Bhi and Alo*Bhi
#pragma unroll
            for (int mt = 0; mt < 2; mt++) {
                int am = wm * 32 + mt * 16 + g;
                afl[0] = *(const uint32_t*)&Alo[am][kb];
                afl[1] = *(const uint32_t*)&Alo[am + 8][kb];
                afl[2] = *(const uint32_t*)&Alo[am][kb + 8];
                afl[3] = *(const uint32_t*)&Alo[am + 8][kb + 8];
#pragma unroll
                for (int nt = 0; nt < 8; nt++) {
                    mma_bf16(acc[mt][nt], afh[mt], bf[nt]);
                    mma_bf16(acc[mt][nt], afl, bf[nt]);
                }
            }
            // pass 3: Ahi*Blo
#pragma unroll
            for (int nt = 0; nt < 8; nt++) {
                int nn = wn * 64 + nt * 8 + g;
                bf[nt][0] = *(const uint32_t*)&Blo[nn][kb];
                bf[nt][1] = *(const uint32_t*)&Blo[nn][kb + 8];
            }
#pragma unroll
            for (int mt = 0; mt < 2; mt++)
#pragma unroll
                for (int nt = 0; nt < 8; nt++)
                    mma_bf16(acc[mt][nt], afh[mt], bf[nt]);
        }
    }

    // epilogue: acc -> out (+bias)
#pragma unroll
    for (int mt = 0; mt < 2; mt++) {
        int row = m0 + wm * 32 + mt * 16 + g;
#pragma unroll
        for (int nt = 0; nt < 8; nt++) {
            int col = wn * 64 + nt * 8 + tig * 2;
            float2 bb = *(const float2*)&bias[col];
            if (row < n) {
                float2 r0 = make_float2(acc[mt][nt][0] + bb.x, acc[mt][nt][1] + bb.y);
                *(float2*)&out[(size_t)row * 128 + col] = r0;
            }
            if (row + 8 < n) {
                float2 r1 = make_float2(acc[mt][nt][2] + bb.x, acc[mt][nt][3] + bb.y);
                *(float2*)&out[(size_t)(row + 8) * 128 + col] = r1;
            }
        }
    }
}

// ---------------- launch ----------------
extern "C" void kernel_launch(void* const* d_in, const int* in_sizes, int n_in,
                              void* d_out, int out_size) {
    const float* x    = (const float*)d_in[0];
    const int*   ei   = (const int*)d_in[1];      // int32 (JAX x64 disabled)
    const float* W    = (const float*)d_in[2];
    const float* bias = (const float*)d_in[3];
    float*       out  = (float*)d_out;

    int n = in_sizes[0] / D;      // 50000
    int E = in_sizes[1] / 2;      // 600000

    // CSR build (by destination)
    zero_kernel<<<(MAXN + 255) / 256, 256>>>();
    degree_kernel<<<(E + 255) / 256, 256>>>(ei, E);
    scan_kernel<<<1, 1024>>>();
    fill_kernel<<<(E + 255) / 256, 256>>>(ei, E);

    // two mean-propagation hops
    int hop_blocks = (n * 32 + 255) / 256;
    hop_kernel<<<hop_blocks, 256>>>(x, 0, n);
    hop_kernel<<<hop_blocks, 256>>>(x, 1, n);

    // split-bf16 HMMA GEMM (mma.sync, portable to plain sm_103 target)
    hmma_gemm_kernel<<<(n + 127) / 128, 256>>>(x, W, bias, out, n);
}